// round 7
// baseline (speedup 1.0000x reference)
#include <cuda_runtime.h>
#include <cuda_fp16.h>

// LogicDense: out[i][j] = c0 + c1*a + c2*b + c3*a*b
//   a = x[i, idx0[j]], b = x[i, idx1[j]]
//
// R7 vs R6 (39.2 us main; occ fell to 42% at 48 regs / 512 thr -> latency-bound):
//  - blockDim 512 -> 448 with __launch_bounds__(448, 3): 448*3*48 = 64512 regs
//    and 3*64 KiB smem both fit -> 3 blocks/SM, occ 42 -> ~65%, same inner loop.
//  - Output stores use __stcs (evict-first): out is write-once; keeps L2 for
//    the per-column table records (~128 MiB of L2 hits) and x rows.
//  - Everything else unchanged: fp16 ROWS=8 swizzled tile, fused 16-B records
//    in even/odd split arrays, column-pair per thread with STG.64.

#define ROWS 8
#define THREADS 448
#define MAX_OUT 16384

__device__ uint4 g_tabE[MAX_OUT / 2];  // records for even columns 2p
__device__ uint4 g_tabO[MAX_OUT / 2];  // records for odd  columns 2p+1
// record: .x=h2(c0,c1) .y=h2(c2,c3) .z=offA|offB<<16 .w=pad

__constant__ float c_T[64] = {
    0.f, 0.f, 0.f, 0.f,
    0.f, 0.f, 0.f, 1.f,
    0.f, 1.f, 0.f,-1.f,
    0.f, 1.f, 0.f, 0.f,
    0.f, 0.f, 1.f,-1.f,
    0.f, 0.f, 1.f, 0.f,
    0.f, 1.f, 1.f,-2.f,
    0.f, 1.f, 1.f,-1.f,
    1.f,-1.f,-1.f, 1.f,
    1.f,-1.f,-1.f, 2.f,
    1.f, 0.f,-1.f, 0.f,
    1.f, 0.f,-1.f, 1.f,
    1.f,-1.f, 0.f, 0.f,
    1.f,-1.f, 0.f, 1.f,
    1.f, 0.f, 0.f,-1.f,
    1.f, 0.f, 0.f, 0.f
};

__device__ __forceinline__ int swz_off(int idx) {
    // half-index of the 8-row group of element idx in the swizzled tile
    return (idx << 3) ^ (((idx >> 3) & 7) << 3);
}

__global__ void precompute_kernel(const void* __restrict__ idx_raw,
                                  const float* __restrict__ w,
                                  int out_dim) {
    __shared__ unsigned int red[128];
    __shared__ int s_is64;

    // int64-vs-int32 detection: OR of odd u32 words == 0 iff int64 high words.
    const unsigned int* u = (const unsigned int*)idx_raw;
    int n_chk = 2 * out_dim;
    if (n_chk > 512) n_chk = 512;
    unsigned int v = 0;
    for (int k = 1 + 2 * (int)threadIdx.x; k < n_chk; k += 2 * (int)blockDim.x)
        v |= u[k];
    red[threadIdx.x] = v;
    __syncthreads();
    for (int s = 64; s > 0; s >>= 1) {
        if ((int)threadIdx.x < s) red[threadIdx.x] |= red[threadIdx.x + s];
        __syncthreads();
    }
    if (threadIdx.x == 0) s_is64 = (red[0] == 0u) ? 1 : 0;
    __syncthreads();
    const int is64 = s_is64;

    int j = blockIdx.x * blockDim.x + threadIdx.x;
    if (j >= out_dim) return;

    float wv[16];
    float m = -1e30f;
#pragma unroll
    for (int k = 0; k < 16; k++) {
        wv[k] = w[j * 16 + k];
        m = fmaxf(m, wv[k]);
    }
    float s = 0.f;
#pragma unroll
    for (int k = 0; k < 16; k++) {
        wv[k] = __expf(wv[k] - m);
        s += wv[k];
    }
    float inv = 1.f / s;
    float c0 = 0.f, c1 = 0.f, c2 = 0.f, c3 = 0.f;
#pragma unroll
    for (int k = 0; k < 16; k++) {
        float p = wv[k] * inv;
        c0 = fmaf(p, c_T[4 * k + 0], c0);
        c1 = fmaf(p, c_T[4 * k + 1], c1);
        c2 = fmaf(p, c_T[4 * k + 2], c2);
        c3 = fmaf(p, c_T[4 * k + 3], c3);
    }

    int i0, i1;
    if (is64) {
        const long long* p = (const long long*)idx_raw;
        i0 = (int)p[j];
        i1 = (int)p[out_dim + j];
    } else {
        const int* p = (const int*)idx_raw;
        i0 = p[j];
        i1 = p[out_dim + j];
    }

    __half2 c01 = __floats2half2_rn(c0, c1);
    __half2 c23 = __floats2half2_rn(c2, c3);
    uint4 rec;
    rec.x = *(unsigned int*)&c01;
    rec.y = *(unsigned int*)&c23;
    rec.z = (unsigned int)swz_off(i0) | ((unsigned int)swz_off(i1) << 16);
    rec.w = 0u;
    if (j & 1) g_tabO[j >> 1] = rec;
    else       g_tabE[j >> 1] = rec;
}

__device__ __forceinline__ unsigned int pack_h2(float lo, float hi) {
    __half2 h = __floats2half2_rn(lo, hi);
    return *(unsigned int*)&h;
}

__device__ __forceinline__ float2 h22f2(unsigned int u) {
    return __half22float2(*(const __half2*)&u);
}

template <bool FULL>
__global__ __launch_bounds__(THREADS, 3) void logic_main_kernel(
    const float* __restrict__ x,
    float* __restrict__ out,
    int in_dim, int out_dim, int batch) {
    extern __shared__ __half sh[];   // in_dim * 8 halfs (64 KiB @ 4096), swizzled

    const int rb = blockIdx.x * ROWS;
    const int nr = FULL ? ROWS : min(ROWS, batch - rb);

    // ---- stage 8 rows: LDG.128 x8, convert to half, repack, STS.128 x4 ----
    {
        const int n4 = in_dim >> 2;   // element-chunks of 4
        const float* xb = x + (size_t)rb * in_dim;
        for (int i = threadIdx.x; i < n4; i += blockDim.x) {
            float4 r[ROWS];
#pragma unroll
            for (int rr = 0; rr < ROWS; rr++) {
                int row = (FULL || rr < nr) ? rr : 0;
                r[rr] = *(const float4*)(xb + (size_t)row * in_dim + (i << 2));
            }
#pragma unroll
            for (int k = 0; k < 4; k++) {
                uint4 pk;
                pk.x = pack_h2((&r[0].x)[k], (&r[1].x)[k]);
                pk.y = pack_h2((&r[2].x)[k], (&r[3].x)[k]);
                pk.z = pack_h2((&r[4].x)[k], (&r[5].x)[k]);
                pk.w = pack_h2((&r[6].x)[k], (&r[7].x)[k]);
                const int idx = (i << 2) + k;
                *(uint4*)(sh + swz_off(idx)) = pk;
            }
        }
    }
    __syncthreads();

    // ---- compute: column pair per thread, STG.64 evict-first stores ----
    const int npair = out_dim >> 1;
    for (int q = threadIdx.x; q < npair; q += blockDim.x) {
        const uint4 rE = g_tabE[q];
        const uint4 rO = g_tabO[q];

        const uint4 aE = *(const uint4*)(sh + (rE.z & 0xFFFFu));
        const uint4 bE = *(const uint4*)(sh + (rE.z >> 16));
        const uint4 aO = *(const uint4*)(sh + (rO.z & 0xFFFFu));
        const uint4 bO = *(const uint4*)(sh + (rO.z >> 16));

        const float2 cE01 = h22f2(rE.x);
        const float2 cE23 = h22f2(rE.y);
        const float2 cO01 = h22f2(rO.x);
        const float2 cO23 = h22f2(rO.y);

        float* op = out + (size_t)rb * out_dim + 2 * q;
#pragma unroll
        for (int r2 = 0; r2 < 4; r2++) {
            const float2 vaE = h22f2((&aE.x)[r2]);
            const float2 vbE = h22f2((&bE.x)[r2]);
            const float2 vaO = h22f2((&aO.x)[r2]);
            const float2 vbO = h22f2((&bO.x)[r2]);

            // row 2*r2
            if (FULL || 2 * r2 < nr) {
                float2 res;
                res.x = fmaf(vaE.x, fmaf(vbE.x, cE23.y, cE01.y),
                             fmaf(vbE.x, cE23.x, cE01.x));
                res.y = fmaf(vaO.x, fmaf(vbO.x, cO23.y, cO01.y),
                             fmaf(vbO.x, cO23.x, cO01.x));
                __stcs((float2*)(op + (size_t)(2 * r2) * out_dim), res);
            }
            // row 2*r2+1
            if (FULL || 2 * r2 + 1 < nr) {
                float2 res;
                res.x = fmaf(vaE.y, fmaf(vbE.y, cE23.y, cE01.y),
                             fmaf(vbE.y, cE23.x, cE01.x));
                res.y = fmaf(vaO.y, fmaf(vbO.y, cO23.y, cO01.y),
                             fmaf(vbO.y, cO23.x, cO01.x));
                __stcs((float2*)(op + (size_t)(2 * r2 + 1) * out_dim), res);
            }
        }
    }
}

extern "C" void kernel_launch(void* const* d_in, const int* in_sizes, int n_in,
                              void* d_out, int out_size) {
    const float* x   = (const float*)d_in[0];
    const void*  idx = d_in[1];
    const float* w   = (const float*)d_in[2];
    float*       out = (float*)d_out;

    const int out_dim = in_sizes[2] / 16;         // weight is (out_dim, 16)
    const int batch   = out_size / out_dim;       // out is (batch, out_dim)
    const int in_dim  = in_sizes[0] / batch;      // x is (batch, in_dim)

    precompute_kernel<<<(out_dim + 127) / 128, 128>>>(idx, w, out_dim);

    const size_t smem = (size_t)in_dim * ROWS * sizeof(__half);   // 64 KiB @ 4096
    const int grid = (batch + ROWS - 1) / ROWS;

    if (batch % ROWS == 0) {
        cudaFuncSetAttribute(logic_main_kernel<true>,
                             cudaFuncAttributeMaxDynamicSharedMemorySize, (int)smem);
        logic_main_kernel<true><<<grid, THREADS, smem>>>(x, out, in_dim, out_dim, batch);
    } else {
        cudaFuncSetAttribute(logic_main_kernel<false>,
                             cudaFuncAttributeMaxDynamicSharedMemorySize, (int)smem);
        logic_main_kernel<false><<<grid, THREADS, smem>>>(x, out, in_dim, out_dim, batch);
    }
}

// round 9
// speedup vs baseline: 1.1159x; 1.1159x over previous
#include <cuda_runtime.h>
#include <cuda_fp16.h>

// LogicDense: out[i][j] = c0 + c1*a + c2*b + c3*a*b
//   a = x[i, idx0[j]], b = x[i, idx1[j]]
//
// R9 = R8 resubmitted (R8 hit an infra container failure; kernel never ran).
// R8 = R6 (best: 39.2 us main) + __launch_bounds__(512, 3).
// R7 post-mortem: __stcs REGRESSED DRAM efficiency (BW 3657->3015 GB/s) and
// 448 threads didn't deliver occupancy -> both reverted. This round changes
// ONE thing vs R6: pin 3 blocks/SM at 512 threads (ptxas target 42 regs;
// R7 showed the kernel compiles at 40 regs w/o heavy spills), raising
// occ 42% -> ~63% to cover the ~234cyc L2-hit latency on table records.

#define ROWS 8
#define THREADS 512
#define MAX_OUT 16384

__device__ uint4 g_tabE[MAX_OUT / 2];  // records for even columns 2p
__device__ uint4 g_tabO[MAX_OUT / 2];  // records for odd  columns 2p+1
// record: .x=h2(c0,c1) .y=h2(c2,c3) .z=offA|offB<<16 .w=pad

__constant__ float c_T[64] = {
    0.f, 0.f, 0.f, 0.f,
    0.f, 0.f, 0.f, 1.f,
    0.f, 1.f, 0.f,-1.f,
    0.f, 1.f, 0.f, 0.f,
    0.f, 0.f, 1.f,-1.f,
    0.f, 0.f, 1.f, 0.f,
    0.f, 1.f, 1.f,-2.f,
    0.f, 1.f, 1.f,-1.f,
    1.f,-1.f,-1.f, 1.f,
    1.f,-1.f,-1.f, 2.f,
    1.f, 0.f,-1.f, 0.f,
    1.f, 0.f,-1.f, 1.f,
    1.f,-1.f, 0.f, 0.f,
    1.f,-1.f, 0.f, 1.f,
    1.f, 0.f, 0.f,-1.f,
    1.f, 0.f, 0.f, 0.f
};

__device__ __forceinline__ int swz_off(int idx) {
    // half-index of the 8-row group of element idx in the swizzled tile
    return (idx << 3) ^ (((idx >> 3) & 7) << 3);
}

__global__ void precompute_kernel(const void* __restrict__ idx_raw,
                                  const float* __restrict__ w,
                                  int out_dim) {
    __shared__ unsigned int red[128];
    __shared__ int s_is64;

    // int64-vs-int32 detection: OR of odd u32 words == 0 iff int64 high words.
    const unsigned int* u = (const unsigned int*)idx_raw;
    int n_chk = 2 * out_dim;
    if (n_chk > 512) n_chk = 512;
    unsigned int v = 0;
    for (int k = 1 + 2 * (int)threadIdx.x; k < n_chk; k += 2 * (int)blockDim.x)
        v |= u[k];
    red[threadIdx.x] = v;
    __syncthreads();
    for (int s = 64; s > 0; s >>= 1) {
        if ((int)threadIdx.x < s) red[threadIdx.x] |= red[threadIdx.x + s];
        __syncthreads();
    }
    if (threadIdx.x == 0) s_is64 = (red[0] == 0u) ? 1 : 0;
    __syncthreads();
    const int is64 = s_is64;

    int j = blockIdx.x * blockDim.x + threadIdx.x;
    if (j >= out_dim) return;

    float wv[16];
    float m = -1e30f;
#pragma unroll
    for (int k = 0; k < 16; k++) {
        wv[k] = w[j * 16 + k];
        m = fmaxf(m, wv[k]);
    }
    float s = 0.f;
#pragma unroll
    for (int k = 0; k < 16; k++) {
        wv[k] = __expf(wv[k] - m);
        s += wv[k];
    }
    float inv = 1.f / s;
    float c0 = 0.f, c1 = 0.f, c2 = 0.f, c3 = 0.f;
#pragma unroll
    for (int k = 0; k < 16; k++) {
        float p = wv[k] * inv;
        c0 = fmaf(p, c_T[4 * k + 0], c0);
        c1 = fmaf(p, c_T[4 * k + 1], c1);
        c2 = fmaf(p, c_T[4 * k + 2], c2);
        c3 = fmaf(p, c_T[4 * k + 3], c3);
    }

    int i0, i1;
    if (is64) {
        const long long* p = (const long long*)idx_raw;
        i0 = (int)p[j];
        i1 = (int)p[out_dim + j];
    } else {
        const int* p = (const int*)idx_raw;
        i0 = p[j];
        i1 = p[out_dim + j];
    }

    __half2 c01 = __floats2half2_rn(c0, c1);
    __half2 c23 = __floats2half2_rn(c2, c3);
    uint4 rec;
    rec.x = *(unsigned int*)&c01;
    rec.y = *(unsigned int*)&c23;
    rec.z = (unsigned int)swz_off(i0) | ((unsigned int)swz_off(i1) << 16);
    rec.w = 0u;
    if (j & 1) g_tabO[j >> 1] = rec;
    else       g_tabE[j >> 1] = rec;
}

__device__ __forceinline__ unsigned int pack_h2(float lo, float hi) {
    __half2 h = __floats2half2_rn(lo, hi);
    return *(unsigned int*)&h;
}

__device__ __forceinline__ float2 h22f2(unsigned int u) {
    return __half22float2(*(const __half2*)&u);
}

template <bool FULL>
__global__ __launch_bounds__(THREADS, 3) void logic_main_kernel(
    const float* __restrict__ x,
    float* __restrict__ out,
    int in_dim, int out_dim, int batch) {
    extern __shared__ __half sh[];   // in_dim * 8 halfs (64 KiB @ 4096), swizzled

    const int rb = blockIdx.x * ROWS;
    const int nr = FULL ? ROWS : min(ROWS, batch - rb);

    // ---- stage 8 rows: LDG.128 x8, convert to half, repack, STS.128 x4 ----
    {
        const int n4 = in_dim >> 2;   // element-chunks of 4
        const float* xb = x + (size_t)rb * in_dim;
        for (int i = threadIdx.x; i < n4; i += blockDim.x) {
            float4 r[ROWS];
#pragma unroll
            for (int rr = 0; rr < ROWS; rr++) {
                int row = (FULL || rr < nr) ? rr : 0;
                r[rr] = *(const float4*)(xb + (size_t)row * in_dim + (i << 2));
            }
#pragma unroll
            for (int k = 0; k < 4; k++) {
                uint4 pk;
                pk.x = pack_h2((&r[0].x)[k], (&r[1].x)[k]);
                pk.y = pack_h2((&r[2].x)[k], (&r[3].x)[k]);
                pk.z = pack_h2((&r[4].x)[k], (&r[5].x)[k]);
                pk.w = pack_h2((&r[6].x)[k], (&r[7].x)[k]);
                const int idx = (i << 2) + k;
                *(uint4*)(sh + swz_off(idx)) = pk;
            }
        }
    }
    __syncthreads();

    // ---- compute: column pair per thread, STG.64 stores ----
    const int npair = out_dim >> 1;
    for (int q = threadIdx.x; q < npair; q += blockDim.x) {
        const uint4 rE = g_tabE[q];
        const uint4 rO = g_tabO[q];

        const uint4 aE = *(const uint4*)(sh + (rE.z & 0xFFFFu));
        const uint4 bE = *(const uint4*)(sh + (rE.z >> 16));
        const uint4 aO = *(const uint4*)(sh + (rO.z & 0xFFFFu));
        const uint4 bO = *(const uint4*)(sh + (rO.z >> 16));

        const float2 cE01 = h22f2(rE.x);
        const float2 cE23 = h22f2(rE.y);
        const float2 cO01 = h22f2(rO.x);
        const float2 cO23 = h22f2(rO.y);

        float* op = out + (size_t)rb * out_dim + 2 * q;
#pragma unroll
        for (int r2 = 0; r2 < 4; r2++) {
            const float2 vaE = h22f2((&aE.x)[r2]);
            const float2 vbE = h22f2((&bE.x)[r2]);
            const float2 vaO = h22f2((&aO.x)[r2]);
            const float2 vbO = h22f2((&bO.x)[r2]);

            // row 2*r2
            if (FULL || 2 * r2 < nr) {
                float2 res;
                res.x = fmaf(vaE.x, fmaf(vbE.x, cE23.y, cE01.y),
                             fmaf(vbE.x, cE23.x, cE01.x));
                res.y = fmaf(vaO.x, fmaf(vbO.x, cO23.y, cO01.y),
                             fmaf(vbO.x, cO23.x, cO01.x));
                *(float2*)(op + (size_t)(2 * r2) * out_dim) = res;
            }
            // row 2*r2+1
            if (FULL || 2 * r2 + 1 < nr) {
                float2 res;
                res.x = fmaf(vaE.y, fmaf(vbE.y, cE23.y, cE01.y),
                             fmaf(vbE.y, cE23.x, cE01.x));
                res.y = fmaf(vaO.y, fmaf(vbO.y, cO23.y, cO01.y),
                             fmaf(vbO.y, cO23.x, cO01.x));
                *(float2*)(op + (size_t)(2 * r2 + 1) * out_dim) = res;
            }
        }
    }
}

extern "C" void kernel_launch(void* const* d_in, const int* in_sizes, int n_in,
                              void* d_out, int out_size) {
    const float* x   = (const float*)d_in[0];
    const void*  idx = d_in[1];
    const float* w   = (const float*)d_in[2];
    float*       out = (float*)d_out;

    const int out_dim = in_sizes[2] / 16;         // weight is (out_dim, 16)
    const int batch   = out_size / out_dim;       // out is (batch, out_dim)
    const int in_dim  = in_sizes[0] / batch;      // x is (batch, in_dim)

    precompute_kernel<<<(out_dim + 127) / 128, 128>>>(idx, w, out_dim);

    const size_t smem = (size_t)in_dim * ROWS * sizeof(__half);   // 64 KiB @ 4096
    const int grid = (batch + ROWS - 1) / ROWS;

    if (batch % ROWS == 0) {
        cudaFuncSetAttribute(logic_main_kernel<true>,
                             cudaFuncAttributeMaxDynamicSharedMemorySize, (int)smem);
        logic_main_kernel<true><<<grid, THREADS, smem>>>(x, out, in_dim, out_dim, batch);
    } else {
        cudaFuncSetAttribute(logic_main_kernel<false>,
                             cudaFuncAttributeMaxDynamicSharedMemorySize, (int)smem);
        logic_main_kernel<false><<<grid, THREADS, smem>>>(x, out, in_dim, out_dim, batch);
    }
}

// round 10
// speedup vs baseline: 1.2113x; 1.0855x over previous
#include <cuda_runtime.h>
#include <cuda_fp16.h>

// LogicDense: out[i][j] = c0 + c1*a + c2*b + c3*a*b
//   a = x[i, idx0[j]], b = x[i, idx1[j]]
//
// R10 vs R6 (best: 39.2 us main, 48 regs, occ 42%):
// R9 falsified "squeeze regs for occupancy": occ 63% @ 40 regs REGRESSED to
// 45.7 us. The 48-reg codegen is worth more than 20 occ points.
// This round: __launch_bounds__(384, 3) -> reg budget 56 >= 48 (NO squeeze),
// smem 3 x 64 KiB = 192 <= 228 KiB -> 3 blocks/SM, 1152 thr/SM, occ 56%
// at the SAME 48-reg code. Single change vs R6; loops tolerate 384-raggedness.

#define ROWS 8
#define THREADS 384
#define MAX_OUT 16384

__device__ uint4 g_tabE[MAX_OUT / 2];  // records for even columns 2p
__device__ uint4 g_tabO[MAX_OUT / 2];  // records for odd  columns 2p+1
// record: .x=h2(c0,c1) .y=h2(c2,c3) .z=offA|offB<<16 .w=pad

__constant__ float c_T[64] = {
    0.f, 0.f, 0.f, 0.f,
    0.f, 0.f, 0.f, 1.f,
    0.f, 1.f, 0.f,-1.f,
    0.f, 1.f, 0.f, 0.f,
    0.f, 0.f, 1.f,-1.f,
    0.f, 0.f, 1.f, 0.f,
    0.f, 1.f, 1.f,-2.f,
    0.f, 1.f, 1.f,-1.f,
    1.f,-1.f,-1.f, 1.f,
    1.f,-1.f,-1.f, 2.f,
    1.f, 0.f,-1.f, 0.f,
    1.f, 0.f,-1.f, 1.f,
    1.f,-1.f, 0.f, 0.f,
    1.f,-1.f, 0.f, 1.f,
    1.f, 0.f, 0.f,-1.f,
    1.f, 0.f, 0.f, 0.f
};

__device__ __forceinline__ int swz_off(int idx) {
    // half-index of the 8-row group of element idx in the swizzled tile
    return (idx << 3) ^ (((idx >> 3) & 7) << 3);
}

__global__ void precompute_kernel(const void* __restrict__ idx_raw,
                                  const float* __restrict__ w,
                                  int out_dim) {
    __shared__ unsigned int red[128];
    __shared__ int s_is64;

    // int64-vs-int32 detection: OR of odd u32 words == 0 iff int64 high words.
    const unsigned int* u = (const unsigned int*)idx_raw;
    int n_chk = 2 * out_dim;
    if (n_chk > 512) n_chk = 512;
    unsigned int v = 0;
    for (int k = 1 + 2 * (int)threadIdx.x; k < n_chk; k += 2 * (int)blockDim.x)
        v |= u[k];
    red[threadIdx.x] = v;
    __syncthreads();
    for (int s = 64; s > 0; s >>= 1) {
        if ((int)threadIdx.x < s) red[threadIdx.x] |= red[threadIdx.x + s];
        __syncthreads();
    }
    if (threadIdx.x == 0) s_is64 = (red[0] == 0u) ? 1 : 0;
    __syncthreads();
    const int is64 = s_is64;

    int j = blockIdx.x * blockDim.x + threadIdx.x;
    if (j >= out_dim) return;

    float wv[16];
    float m = -1e30f;
#pragma unroll
    for (int k = 0; k < 16; k++) {
        wv[k] = w[j * 16 + k];
        m = fmaxf(m, wv[k]);
    }
    float s = 0.f;
#pragma unroll
    for (int k = 0; k < 16; k++) {
        wv[k] = __expf(wv[k] - m);
        s += wv[k];
    }
    float inv = 1.f / s;
    float c0 = 0.f, c1 = 0.f, c2 = 0.f, c3 = 0.f;
#pragma unroll
    for (int k = 0; k < 16; k++) {
        float p = wv[k] * inv;
        c0 = fmaf(p, c_T[4 * k + 0], c0);
        c1 = fmaf(p, c_T[4 * k + 1], c1);
        c2 = fmaf(p, c_T[4 * k + 2], c2);
        c3 = fmaf(p, c_T[4 * k + 3], c3);
    }

    int i0, i1;
    if (is64) {
        const long long* p = (const long long*)idx_raw;
        i0 = (int)p[j];
        i1 = (int)p[out_dim + j];
    } else {
        const int* p = (const int*)idx_raw;
        i0 = p[j];
        i1 = p[out_dim + j];
    }

    __half2 c01 = __floats2half2_rn(c0, c1);
    __half2 c23 = __floats2half2_rn(c2, c3);
    uint4 rec;
    rec.x = *(unsigned int*)&c01;
    rec.y = *(unsigned int*)&c23;
    rec.z = (unsigned int)swz_off(i0) | ((unsigned int)swz_off(i1) << 16);
    rec.w = 0u;
    if (j & 1) g_tabO[j >> 1] = rec;
    else       g_tabE[j >> 1] = rec;
}

__device__ __forceinline__ unsigned int pack_h2(float lo, float hi) {
    __half2 h = __floats2half2_rn(lo, hi);
    return *(unsigned int*)&h;
}

__device__ __forceinline__ float2 h22f2(unsigned int u) {
    return __half22float2(*(const __half2*)&u);
}

template <bool FULL>
__global__ __launch_bounds__(THREADS, 3) void logic_main_kernel(
    const float* __restrict__ x,
    float* __restrict__ out,
    int in_dim, int out_dim, int batch) {
    extern __shared__ __half sh[];   // in_dim * 8 halfs (64 KiB @ 4096), swizzled

    const int rb = blockIdx.x * ROWS;
    const int nr = FULL ? ROWS : min(ROWS, batch - rb);

    // ---- stage 8 rows: LDG.128 x8, convert to half, repack, STS.128 x4 ----
    {
        const int n4 = in_dim >> 2;   // element-chunks of 4
        const float* xb = x + (size_t)rb * in_dim;
        for (int i = threadIdx.x; i < n4; i += blockDim.x) {
            float4 r[ROWS];
#pragma unroll
            for (int rr = 0; rr < ROWS; rr++) {
                int row = (FULL || rr < nr) ? rr : 0;
                r[rr] = *(const float4*)(xb + (size_t)row * in_dim + (i << 2));
            }
#pragma unroll
            for (int k = 0; k < 4; k++) {
                uint4 pk;
                pk.x = pack_h2((&r[0].x)[k], (&r[1].x)[k]);
                pk.y = pack_h2((&r[2].x)[k], (&r[3].x)[k]);
                pk.z = pack_h2((&r[4].x)[k], (&r[5].x)[k]);
                pk.w = pack_h2((&r[6].x)[k], (&r[7].x)[k]);
                const int idx = (i << 2) + k;
                *(uint4*)(sh + swz_off(idx)) = pk;
            }
        }
    }
    __syncthreads();

    // ---- compute: column pair per thread, STG.64 stores ----
    const int npair = out_dim >> 1;
    for (int q = threadIdx.x; q < npair; q += blockDim.x) {
        const uint4 rE = g_tabE[q];
        const uint4 rO = g_tabO[q];

        const uint4 aE = *(const uint4*)(sh + (rE.z & 0xFFFFu));
        const uint4 bE = *(const uint4*)(sh + (rE.z >> 16));
        const uint4 aO = *(const uint4*)(sh + (rO.z & 0xFFFFu));
        const uint4 bO = *(const uint4*)(sh + (rO.z >> 16));

        const float2 cE01 = h22f2(rE.x);
        const float2 cE23 = h22f2(rE.y);
        const float2 cO01 = h22f2(rO.x);
        const float2 cO23 = h22f2(rO.y);

        float* op = out + (size_t)rb * out_dim + 2 * q;
#pragma unroll
        for (int r2 = 0; r2 < 4; r2++) {
            const float2 vaE = h22f2((&aE.x)[r2]);
            const float2 vbE = h22f2((&bE.x)[r2]);
            const float2 vaO = h22f2((&aO.x)[r2]);
            const float2 vbO = h22f2((&bO.x)[r2]);

            // row 2*r2
            if (FULL || 2 * r2 < nr) {
                float2 res;
                res.x = fmaf(vaE.x, fmaf(vbE.x, cE23.y, cE01.y),
                             fmaf(vbE.x, cE23.x, cE01.x));
                res.y = fmaf(vaO.x, fmaf(vbO.x, cO23.y, cO01.y),
                             fmaf(vbO.x, cO23.x, cO01.x));
                *(float2*)(op + (size_t)(2 * r2) * out_dim) = res;
            }
            // row 2*r2+1
            if (FULL || 2 * r2 + 1 < nr) {
                float2 res;
                res.x = fmaf(vaE.y, fmaf(vbE.y, cE23.y, cE01.y),
                             fmaf(vbE.y, cE23.x, cE01.x));
                res.y = fmaf(vaO.y, fmaf(vbO.y, cO23.y, cO01.y),
                             fmaf(vbO.y, cO23.x, cO01.x));
                *(float2*)(op + (size_t)(2 * r2 + 1) * out_dim) = res;
            }
        }
    }
}

extern "C" void kernel_launch(void* const* d_in, const int* in_sizes, int n_in,
                              void* d_out, int out_size) {
    const float* x   = (const float*)d_in[0];
    const void*  idx = d_in[1];
    const float* w   = (const float*)d_in[2];
    float*       out = (float*)d_out;

    const int out_dim = in_sizes[2] / 16;         // weight is (out_dim, 16)
    const int batch   = out_size / out_dim;       // out is (batch, out_dim)
    const int in_dim  = in_sizes[0] / batch;      // x is (batch, in_dim)

    precompute_kernel<<<(out_dim + 127) / 128, 128>>>(idx, w, out_dim);

    const size_t smem = (size_t)in_dim * ROWS * sizeof(__half);   // 64 KiB @ 4096
    const int grid = (batch + ROWS - 1) / ROWS;

    if (batch % ROWS == 0) {
        cudaFuncSetAttribute(logic_main_kernel<true>,
                             cudaFuncAttributeMaxDynamicSharedMemorySize, (int)smem);
        logic_main_kernel<true><<<grid, THREADS, smem>>>(x, out, in_dim, out_dim, batch);
    } else {
        cudaFuncSetAttribute(logic_main_kernel<false>,
                             cudaFuncAttributeMaxDynamicSharedMemorySize, (int)smem);
        logic_main_kernel<false><<<grid, THREADS, smem>>>(x, out, in_dim, out_dim, batch);
    }
}